// round 16
// baseline (speedup 1.0000x reference)
#include <cuda_runtime.h>
#include <math.h>

#define BQ   4
#define LQ   60
#define HQ   768
#define IQ   1536
#define NQ   16
#define RQ   48
#define NLYR 32
#define BL   240

// ---------------- device scratch (~21 MB) ----------------
__device__ float g_h  [BL * HQ];
__device__ uint2 g_anp[BL * HQ];        // normed A, packed tf32 {hi,lo}
__device__ float g_io [BL * 2 * IQ];    // in-proj out: hs | gate
__device__ float g_hs2[BL * IQ];        // conv+silu
__device__ float g_sp [BL * 80];
__device__ uint2 g_ycp[BL * IQ];        // y, packed tf32 {hi,lo}
__device__ float g_hf [BL * HQ];
__device__ float g_sc [BL * 4];
__device__ float g_m  [BQ * 4 * HQ];
__device__ float g_xpT[NLYR * 80 * IQ]; // xp_w transposed [l][o][k]
__device__ int   g_cnt[15];             // per-row-block completion counters

__device__ __forceinline__ unsigned su32(const void* p) {
    unsigned a;
    asm("{ .reg .u64 t; cvta.to.shared.u64 t, %1; cvt.u32.u64 %0, t; }" : "=r"(a) : "l"(p));
    return a;
}
#define CPA16(dst, src) asm volatile("cp.async.cg.shared.global [%0], [%1], 16;" :: "r"(dst), "l"(src))
#define CPCOMMIT()      asm volatile("cp.async.commit_group;")
#define CPWAIT1()       asm volatile("cp.async.wait_group 1;")

__device__ __forceinline__ unsigned f2tf(float x) {
    unsigned r;
    asm("cvt.rna.tf32.f32 %0, %1;" : "=r"(r) : "f"(x));
    return r;
}
#define MMA8(d, a, b0, b1) \
    asm volatile("mma.sync.aligned.m16n8k8.row.col.f32.tf32.tf32.f32 " \
                 "{%0,%1,%2,%3},{%4,%5,%6,%7},{%8,%9},{%0,%1,%2,%3};" \
                 : "+f"(d[0]), "+f"(d[1]), "+f"(d[2]), "+f"(d[3]) \
                 : "r"(a[0]), "r"(a[1]), "r"(a[2]), "r"(a[3]), "r"(b0), "r"(b1))

// ---------------- xp_w transpose (once per replay) --------------------------
__global__ void k_xt(const float* __restrict__ xp_w) {
    int e = blockIdx.x * 256 + threadIdx.x;
    if (e < NLYR * 80 * IQ) {
        int k = e % IQ;
        int o = (e / IQ) % 80;
        int l = e / (IQ * 80);
        g_xpT[e] = xp_w[((size_t)l * IQ + k) * 80 + o];
    }
}

// ---------------- input MLP (also resets row-block counters) ----------------
__global__ void k_in_mlp(const float* __restrict__ x,
                         const float* __restrict__ iw1, const float* __restrict__ ib1,
                         const float* __restrict__ iw2, const float* __restrict__ ib2,
                         const float* __restrict__ iw3, const float* __restrict__ ib3) {
    int r = blockIdx.x, tid = threadIdx.x;
    if (tid == 0 && r < 15) g_cnt[r] = 0;
    __shared__ float xr[13];
    __shared__ float h1[256];
    __shared__ float h2[256];
    if (tid < 13) xr[tid] = x[r * 13 + tid];
    __syncthreads();
    float a = ib1[tid];
#pragma unroll
    for (int k = 0; k < 13; k++) a += xr[k] * iw1[k * 256 + tid];
    h1[tid] = fmaxf(a, 0.f);
    __syncthreads();
    a = ib2[tid];
    for (int k = 0; k < 256; k++) a += h1[k] * iw2[k * 256 + tid];
    h2[tid] = fmaxf(a, 0.f);
    __syncthreads();
#pragma unroll
    for (int ii = 0; ii < 3; ii++) {
        int c = tid + ii * 256;
        float v = ib3[c];
        for (int k = 0; k < 256; k++) v += h2[k] * iw3[k * 768 + c];
        g_h[r * 768 + c] = v;
    }
}

// ---------------- rmsnorm + tf32 hi/lo pre-split (layer 0 only) -------------
__global__ void k_anorm(const float* __restrict__ norm_w, int l) {
    int r = blockIdx.x, tid = threadIdx.x;
    __shared__ float red[8];
    float v0 = g_h[r * 768 + tid];
    float v1 = g_h[r * 768 + 256 + tid];
    float v2 = g_h[r * 768 + 512 + tid];
    float ss = v0 * v0 + v1 * v1 + v2 * v2;
#pragma unroll
    for (int o = 16; o > 0; o >>= 1) ss += __shfl_xor_sync(0xffffffffu, ss, o);
    if ((tid & 31) == 0) red[tid >> 5] = ss;
    __syncthreads();
    float tot = red[0] + red[1] + red[2] + red[3] + red[4] + red[5] + red[6] + red[7];
    float rstd = rsqrtf(tot * (1.f / 768.f) + 1e-5f);
    const float* nw = norm_w + l * 768;
#pragma unroll
    for (int ii = 0; ii < 3; ii++) {
        int c = tid + ii * 256;
        float v = (ii == 0 ? v0 : (ii == 1 ? v1 : v2)) * rstd * nw[c];
        unsigned h = f2tf(v);
        g_anp[r * 768 + c] = make_uint2(h, f2tf(v - __uint_as_float(h)));
    }
}

// ---------------- in-proj GEMM (tf32 TC, pre-packed A, KTILE=32) ------------
// grid (24,15), 256 thr; block tile 16x128
__global__ void __launch_bounds__(256, 1) k_gemm_in(const float* __restrict__ in_w, int l) {
    __shared__ uint2 Apk[2][16][36];   //  9.2 KB
    __shared__ float Ws [2][32][132];  // 33.8 KB
    const float* W = in_w + (size_t)l * 768 * 3072;
    int tid = threadIdx.x;
    int col0 = blockIdx.x * 128, row0 = blockIdx.y * 16;
    unsigned aA = su32(Apk), aW = su32(Ws);
    int arr = tid >> 4, af2 = (tid & 15) * 2;
    const uint2* asrc = &g_anp[(size_t)(row0 + arr) * 768 + af2];

#define ISSUE_IN(s, k0) do { \
    CPA16(aA + (unsigned)((((s) * 16 + arr) * 36 + af2) * 8), asrc + (k0)); \
    _Pragma("unroll") \
    for (int p = 0; p < 4; p++) { int e = tid + p * 256; int kk = e >> 5, cc = (e & 31) * 4; \
        CPA16(aW + (unsigned)((((s) * 32 + kk) * 132 + cc) * 4), &W[(size_t)((k0) + kk) * 3072 + col0 + cc]); } \
    CPCOMMIT(); } while (0)

    ISSUE_IN(0, 0);
    int lane = tid & 31, wid = tid >> 5;
    int n0 = wid * 16;
    int g = lane >> 2, tg = lane & 3;
    float acc0[4] = {0, 0, 0, 0};
    float acc1[4] = {0, 0, 0, 0};
#pragma unroll 1
    for (int kt = 0; kt < 24; kt++) {
        __syncthreads();
        if (kt < 23) ISSUE_IN((kt + 1) & 1, (kt + 1) * 32); else CPCOMMIT();
        CPWAIT1();
        __syncthreads();
        int s = kt & 1;
#pragma unroll
        for (int ks = 0; ks < 4; ks++) {
            int kb = ks * 8;
            uint2 a0 = Apk[s][g][kb + tg];
            uint2 a1 = Apk[s][g + 8][kb + tg];
            uint2 a2 = Apk[s][g][kb + tg + 4];
            uint2 a3 = Apk[s][g + 8][kb + tg + 4];
            unsigned ah[4] = {a0.x, a1.x, a2.x, a3.x};
            unsigned al[4] = {a0.y, a1.y, a2.y, a3.y};
#pragma unroll
            for (int nf = 0; nf < 2; nf++) {
                int nc = n0 + nf * 8 + g;
                float bf0 = Ws[s][kb + tg][nc];
                float bf1 = Ws[s][kb + tg + 4][nc];
                unsigned bh0 = f2tf(bf0), bl0 = f2tf(bf0 - __uint_as_float(bh0));
                unsigned bh1 = f2tf(bf1), bl1 = f2tf(bf1 - __uint_as_float(bh1));
                float* acc = nf ? acc1 : acc0;
                MMA8(acc, ah, bh0, bh1);
                MMA8(acc, ah, bl0, bl1);
                MMA8(acc, al, bh0, bh1);
            }
        }
    }
#pragma unroll
    for (int nf = 0; nf < 2; nf++) {
        const float* acc = nf ? acc1 : acc0;
        int c = col0 + n0 + nf * 8 + tg * 2;
        size_t o0 = (size_t)(row0 + g) * 3072 + c;
        size_t o1 = (size_t)(row0 + g + 8) * 3072 + c;
        g_io[o0] = acc[0]; g_io[o0 + 1] = acc[1];
        g_io[o1] = acc[2]; g_io[o1 + 1] = acc[3];
    }
#undef ISSUE_IN
}

// ---------------- conv+silu+sp per row (coalesced transposed weights) -------
__global__ void __launch_bounds__(256) k_csp(const float* __restrict__ conv_w,
                                             const float* __restrict__ conv_b, int l) {
    __shared__ float hs2s[1536];
    int tid = threadIdx.x;
    int r = blockIdx.x, t = r % 60;
    int lane = tid & 31, w = tid >> 5;
    const float4* cw4 = (const float4*)(conv_w + (size_t)l * 1536 * 4);
    const float*  cb  = conv_b + l * 1536;
#pragma unroll
    for (int ii = 0; ii < 6; ii++) {
        int i = tid + ii * 256;
        float4 wv = cw4[i];
        const float* hsc = &g_io[(size_t)r * 3072 + i];
        float a = cb[i] + hsc[0] * wv.w;
        if (t >= 1) a += hsc[-3072] * wv.z;
        if (t >= 2) a += hsc[-6144] * wv.y;
        if (t >= 3) a += hsc[-9216] * wv.x;
        float v = a / (1.f + __expf(-a));
        hs2s[i] = v;
        g_hs2[(size_t)r * 1536 + i] = v;
    }
    __syncthreads();
    const float* WT = g_xpT + (size_t)l * 80 * 1536 + (size_t)w * 10 * 1536;
    float acc[10] = {0, 0, 0, 0, 0, 0, 0, 0, 0, 0};
#pragma unroll 2
    for (int k = lane; k < 1536; k += 32) {
        float h = hs2s[k];
#pragma unroll
        for (int j = 0; j < 10; j++) acc[j] = fmaf(h, WT[j * 1536 + k], acc[j]);
    }
#pragma unroll
    for (int j = 0; j < 10; j++) {
        float v = acc[j];
        v += __shfl_xor_sync(0xffffffffu, v, 16);
        v += __shfl_xor_sync(0xffffffffu, v, 8);
        v += __shfl_xor_sync(0xffffffffu, v, 4);
        v += __shfl_xor_sync(0xffffffffu, v, 2);
        v += __shfl_xor_sync(0xffffffffu, v, 1);
        if (lane == 0) g_sp[r * 80 + w * 10 + j] = v;
    }
}

// ---------------- scan: fused dt-proj + softplus + gate + tf32 pack ---------
__global__ void __launch_bounds__(256) k_scan(const float* __restrict__ A_log,
                                              const float* __restrict__ Dp,
                                              const float* __restrict__ dt_w,
                                              const float* __restrict__ dt_b, int l) {
    __shared__ float ssp[60][80];
    __shared__ float shs[60][32];
    __shared__ float sdt[60][32];
    __shared__ float sWd[48][32];
    __shared__ float sdb[32];
    int tid = threadIdx.x;
    int b = blockIdx.x / 48, ic = blockIdx.x % 48, i0 = ic * 32;

    for (int e = tid; e < 1200; e += 256)
        ((float4*)ssp)[e] = ((const float4*)(g_sp + b * 60 * 80))[e];
    for (int e = tid; e < 1920; e += 256) {
        int t = e >> 5, j = e & 31;
        shs[t][j] = g_hs2[(size_t)(b * 60 + t) * 1536 + i0 + j];
    }
    const float* Wd = dt_w + (size_t)l * 48 * 1536;
    for (int e = tid; e < 1536; e += 256) {
        int k = e >> 5, j = e & 31;
        sWd[k][j] = Wd[(size_t)k * 1536 + i0 + j];
    }
    if (tid < 32) sdb[tid] = dt_b[l * 1536 + i0 + tid];
    __syncthreads();

    for (int e = tid; e < 1920; e += 256) {
        int t = e >> 5, j = e & 31;
        float d = sdb[j];
#pragma unroll
        for (int k = 0; k < 48; k++) d = fmaf(ssp[t][k], sWd[k][j], d);
        d = (d > 15.f) ? d : log1pf(__expf(d));
        sdt[t][j] = d;
    }
    __syncthreads();

    if (tid < 128) {
        int p = tid >> 2, nq = tid & 3;
        int i = i0 + p;
        float A[4], st[4] = {0, 0, 0, 0};
        const float* Ap = &A_log[((size_t)l * 1536 + i) * 16 + nq * 4];
#pragma unroll
        for (int j = 0; j < 4; j++) A[j] = -__expf(Ap[j]);
        float Dv = Dp[l * 1536 + i];

        for (int t = 0; t < 60; t++) {
            float dtv = sdt[t][p], hsv = shs[t][p];
            float du = dtv * hsv;
            float ys = 0.f;
#pragma unroll
            for (int j = 0; j < 4; j++) {
                float dA = __expf(dtv * A[j]);
                st[j] = fmaf(dA, st[j], du * ssp[t][48 + nq * 4 + j]);
                ys = fmaf(st[j], ssp[t][64 + nq * 4 + j], ys);
            }
            // shfl_xor is a convergence point: the sdt[t][p] read above is
            // complete in all lanes before the nq==0 write below.
            ys += __shfl_xor_sync(0xffffffffu, ys, 1);
            ys += __shfl_xor_sync(0xffffffffu, ys, 2);
            if (nq == 0) sdt[t][p] = ys + hsv * Dv;
        }
    }
    __syncthreads();

    for (int e = tid; e < 1920; e += 256) {
        int t = e >> 5, j = e & 31;
        float g = g_io[(size_t)(b * 60 + t) * 3072 + 1536 + i0 + j];
        float sg = g / (1.f + __expf(-g));
        float v = sdt[t][j] * sg;
        unsigned h = f2tf(v);
        g_ycp[(size_t)(b * 60 + t) * 1536 + i0 + j] = make_uint2(h, f2tf(v - __uint_as_float(h)));
    }
}

// ---------------- out-proj GEMM + residual + fused next-layer anorm ---------
// grid (12,15), 256 thr; tile 16x64, KTILE=32
__global__ void __launch_bounds__(256) k_gemm_out(const float* __restrict__ out_w,
                                                  const float* __restrict__ norm_w, int l) {
    __shared__ uint2 Apk[2][16][36];   //  9.2 KB
    __shared__ float Ws [2][32][68];   // 17.4 KB
    __shared__ int   isLast;
    const float* W = out_w + (size_t)l * 1536 * 768;
    int tid = threadIdx.x;
    int col0 = blockIdx.x * 64, row0 = blockIdx.y * 16;
    unsigned aA = su32(Apk), aW = su32(Ws);
    int arr = tid >> 4, af2 = (tid & 15) * 2;
    const uint2* asrc = &g_ycp[(size_t)(row0 + arr) * 1536 + af2];

#define ISSUE_OUT(s, k0) do { \
    CPA16(aA + (unsigned)((((s) * 16 + arr) * 36 + af2) * 8), asrc + (k0)); \
    _Pragma("unroll") \
    for (int p = 0; p < 2; p++) { int e = tid + p * 256; int kk = e >> 4, cc = (e & 15) * 4; \
        CPA16(aW + (unsigned)((((s) * 32 + kk) * 68 + cc) * 4), &W[(size_t)((k0) + kk) * 768 + col0 + cc]); } \
    CPCOMMIT(); } while (0)

    ISSUE_OUT(0, 0);
    int lane = tid & 31, wid = tid >> 5;
    int n0 = wid * 8;
    int g = lane >> 2, tg = lane & 3;
    float acc[4] = {0, 0, 0, 0};
#pragma unroll 1
    for (int kt = 0; kt < 48; kt++) {
        __syncthreads();
        if (kt < 47) ISSUE_OUT((kt + 1) & 1, (kt + 1) * 32); else CPCOMMIT();
        CPWAIT1();
        __syncthreads();
        int s = kt & 1;
#pragma unroll
        for (int ks = 0; ks < 4; ks++) {
            int kb = ks * 8;
            uint2 a0 = Apk[s][g][kb + tg];
            uint2 a1 = Apk[s][g + 8][kb + tg];
            uint2 a2 = Apk[s][g][kb + tg + 4];
            uint2 a3 = Apk[s][g + 8][kb + tg + 4];
            unsigned ah[4] = {a0.x, a1.x, a2.x, a3.x};
            unsigned al[4] = {a0.y, a1.y, a2.y, a3.y};
            int nc = n0 + g;
            float bf0 = Ws[s][kb + tg][nc];
            float bf1 = Ws[s][kb + tg + 4][nc];
            unsigned bh0 = f2tf(bf0), bl0 = f2tf(bf0 - __uint_as_float(bh0));
            unsigned bh1 = f2tf(bf1), bl1 = f2tf(bf1 - __uint_as_float(bh1));
            MMA8(acc, ah, bh0, bh1);
            MMA8(acc, ah, bl0, bl1);
            MMA8(acc, al, bh0, bh1);
        }
    }
    {
        int c = col0 + n0 + tg * 2;
        size_t o0 = (size_t)(row0 + g) * 768 + c;
        size_t o1 = (size_t)(row0 + g + 8) * 768 + c;
        g_h[o0]     += acc[0];
        g_h[o0 + 1] += acc[1];
        g_h[o1]     += acc[2];
        g_h[o1 + 1] += acc[3];
    }
#undef ISSUE_OUT

    // ---- last-block-per-row-block: anorm for next layer -------------------
    __threadfence();
    if (tid == 0) {
        int v = atomicAdd(&g_cnt[blockIdx.y], 1);
        isLast = (v == 12 * l + 11) ? 1 : 0;
    }
    __syncthreads();
    if (isLast && l < NLYR - 1) {
        const float* nw = norm_w + (l + 1) * 768;
        int w = tid >> 5;
#pragma unroll
        for (int rr = w; rr < 16; rr += 8) {
            int r = row0 + rr;
            const float* hr = &g_h[(size_t)r * 768];
            float ss = 0.f;
#pragma unroll
            for (int k = lane; k < 768; k += 32) { float v = hr[k]; ss += v * v; }
#pragma unroll
            for (int o = 16; o > 0; o >>= 1) ss += __shfl_xor_sync(0xffffffffu, ss, o);
            float rstd = rsqrtf(__shfl_sync(0xffffffffu, ss, 0) * (1.f / 768.f) + 1e-5f);
#pragma unroll
            for (int k = lane; k < 768; k += 32) {
                float v = hr[k] * rstd * nw[k];
                unsigned h = f2tf(v);
                g_anp[(size_t)r * 768 + k] = make_uint2(h, f2tf(v - __uint_as_float(h)));
            }
        }
    }
}

// ---------------- final rmsnorm + attention logits --------------------------
__global__ void k_final(const float* __restrict__ fnorm_w,
                        const float* __restrict__ ws1, const float* __restrict__ ws2) {
    int r = blockIdx.x, tid = threadIdx.x;
    __shared__ float hf[768];
    __shared__ float al[128];
    __shared__ float red[256];
    float ss = 0.f;
    for (int k = tid; k < 768; k += 256) { float v = g_h[r * 768 + k]; ss += v * v; }
    red[tid] = ss;
    __syncthreads();
    for (int s = 128; s > 0; s >>= 1) { if (tid < s) red[tid] += red[tid + s]; __syncthreads(); }
    float rstd = rsqrtf(red[0] * (1.f / 768.f) + 1e-5f);
#pragma unroll
    for (int ii = 0; ii < 3; ii++) {
        int c = tid + ii * 256;
        float v = g_h[r * 768 + c] * rstd * fnorm_w[c];
        hf[c] = v;
        g_hf[r * 768 + c] = v;
    }
    __syncthreads();
    if (tid < 128) {
        float a = 0.f;
        for (int k = 0; k < 768; k++) a += hf[k] * ws1[k * 128 + tid];
        al[tid] = tanhf(a);
    }
    __syncthreads();
    if (tid < 4) {
        float s = 0.f;
        for (int d = 0; d < 128; d++) s += al[d] * ws2[d * 4 + tid];
        g_sc[r * 4 + tid] = s;
    }
}

// ---------------- softmax + pooling ----------------
__global__ void k_pool() {
    int b = blockIdx.x >> 2, rr = blockIdx.x & 3;
    int tid = threadIdx.x;
    __shared__ float att[60];
    __shared__ float mx_s, inv_s;
    if (tid < 60) att[tid] = g_sc[(b * 60 + tid) * 4 + rr];
    __syncthreads();
    if (tid == 0) {
        float m = -1e30f;
        for (int t = 0; t < 60; t++) m = fmaxf(m, att[t]);
        mx_s = m;
    }
    __syncthreads();
    if (tid < 60) att[tid] = __expf(att[tid] - mx_s);
    __syncthreads();
    if (tid == 0) {
        float s = 0.f;
        for (int t = 0; t < 60; t++) s += att[t];
        inv_s = 1.f / s;
    }
    __syncthreads();
    for (int c = tid; c < 768; c += 256) {
        float acc = 0.f;
        for (int t = 0; t < 60; t++) acc += att[t] * g_hf[(b * 60 + t) * 768 + c];
        g_m[b * 3072 + rr * 768 + c] = acc * inv_s;
    }
}

// ---------------- output MLP ----------------
__global__ void k_out_mlp(const float* __restrict__ ow1, const float* __restrict__ ob1,
                          const float* __restrict__ ow2, const float* __restrict__ ob2,
                          const float* __restrict__ ow3, const float* __restrict__ ob3,
                          float* __restrict__ out) {
    int b = blockIdx.x, tid = threadIdx.x;
    __shared__ float o1[256];
    __shared__ float o2[256];
    __shared__ float red[256];
    float a = ob1[tid];
    for (int k = 0; k < 3072; k++) a += g_m[b * 3072 + k] * ow1[k * 256 + tid];
    o1[tid] = fmaxf(a, 0.f);
    __syncthreads();
    a = ob2[tid];
    for (int k = 0; k < 256; k++) a += o1[k] * ow2[k * 256 + tid];
    o2[tid] = fmaxf(a, 0.f);
    __syncthreads();
    red[tid] = o2[tid] * ow3[tid];
    __syncthreads();
    for (int s = 128; s > 0; s >>= 1) { if (tid < s) red[tid] += red[tid + s]; __syncthreads(); }
    if (tid == 0) out[b] = red[0] + ob3[0];
}

// ---------------- launch ----------------
extern "C" void kernel_launch(void* const* d_in, const int* in_sizes, int n_in,
                              void* d_out, int out_size) {
    const float* x      = (const float*)d_in[0];
    const float* iw1    = (const float*)d_in[1];
    const float* ib1    = (const float*)d_in[2];
    const float* iw2    = (const float*)d_in[3];
    const float* ib2    = (const float*)d_in[4];
    const float* iw3    = (const float*)d_in[5];
    const float* ib3    = (const float*)d_in[6];
    const float* norm_w = (const float*)d_in[7];
    const float* in_w   = (const float*)d_in[8];
    const float* conv_w = (const float*)d_in[9];
    const float* conv_b = (const float*)d_in[10];
    const float* xp_w   = (const float*)d_in[11];
    const float* dt_w   = (const float*)d_in[12];
    const float* dt_b   = (const float*)d_in[13];
    const float* A_log  = (const float*)d_in[14];
    const float* Dp     = (const float*)d_in[15];
    const float* out_w  = (const float*)d_in[16];
    const float* fnorm_w= (const float*)d_in[17];
    const float* ws1    = (const float*)d_in[18];
    const float* ws2    = (const float*)d_in[19];
    const float* ow1    = (const float*)d_in[20];
    const float* ob1    = (const float*)d_in[21];
    const float* ow2    = (const float*)d_in[22];
    const float* ob2    = (const float*)d_in[23];
    const float* ow3    = (const float*)d_in[24];
    const float* ob3    = (const float*)d_in[25];

    k_in_mlp<<<BL, 256>>>(x, iw1, ib1, iw2, ib2, iw3, ib3);
    k_xt<<<(NLYR * 80 * IQ + 255) / 256, 256>>>(xp_w);

    for (int l = 0; l < NLYR; l++) {
        if (l == 0) k_anorm<<<BL, 256>>>(norm_w, 0);
        k_gemm_in<<<dim3(24, 15), 256>>>(in_w, l);
        k_csp<<<BL, 256>>>(conv_w, conv_b, l);
        k_scan<<<192, 256>>>(A_log, Dp, dt_w, dt_b, l);
        k_gemm_out<<<dim3(12, 15), 256>>>(out_w, norm_w, l);
    }
    k_final<<<BL, 256>>>(fnorm_w, ws1, ws2);
    k_pool<<<16, 256>>>();
    k_out_mlp<<<4, 256>>>(ow1, ob1, ow2, ob2, ow3, ob3, (float*)d_out);
}

// round 17
// speedup vs baseline: 1.4484x; 1.4484x over previous
#include <cuda_runtime.h>
#include <math.h>

#define BQ   4
#define LQ   60
#define HQ   768
#define IQ   1536
#define NQ   16
#define RQ   48
#define NLYR 32
#define BL   240

// ---------------- device scratch (~21 MB) ----------------
__device__ float g_h  [BL * HQ];
__device__ uint2 g_anp[BL * HQ];        // normed A, packed tf32 {hi,lo}
__device__ float g_io [BL * 2 * IQ];    // in-proj out: hs | gate
__device__ float g_hs2[BL * IQ];        // conv+silu
__device__ float g_sp [BL * 80];
__device__ uint2 g_ycp[BL * IQ];        // y, packed tf32 {hi,lo}
__device__ float g_hf [BL * HQ];
__device__ float g_sc [BL * 4];
__device__ float g_m  [BQ * 4 * HQ];
__device__ float g_xpT[NLYR * 80 * IQ]; // xp_w transposed [l][o][k]

__device__ __forceinline__ unsigned su32(const void* p) {
    unsigned a;
    asm("{ .reg .u64 t; cvta.to.shared.u64 t, %1; cvt.u32.u64 %0, t; }" : "=r"(a) : "l"(p));
    return a;
}
#define CPA16(dst, src) asm volatile("cp.async.cg.shared.global [%0], [%1], 16;" :: "r"(dst), "l"(src))
#define CPCOMMIT()      asm volatile("cp.async.commit_group;")
#define CPWAIT1()       asm volatile("cp.async.wait_group 1;")

__device__ __forceinline__ unsigned f2tf(float x) {
    unsigned r;
    asm("cvt.rna.tf32.f32 %0, %1;" : "=r"(r) : "f"(x));
    return r;
}
#define MMA8(d, a, b0, b1) \
    asm volatile("mma.sync.aligned.m16n8k8.row.col.f32.tf32.tf32.f32 " \
                 "{%0,%1,%2,%3},{%4,%5,%6,%7},{%8,%9},{%0,%1,%2,%3};" \
                 : "+f"(d[0]), "+f"(d[1]), "+f"(d[2]), "+f"(d[3]) \
                 : "r"(a[0]), "r"(a[1]), "r"(a[2]), "r"(a[3]), "r"(b0), "r"(b1))

// ---------------- xp_w transpose (once per replay) --------------------------
__global__ void k_xt(const float* __restrict__ xp_w) {
    int e = blockIdx.x * 256 + threadIdx.x;
    if (e < NLYR * 80 * IQ) {
        int k = e % IQ;
        int o = (e / IQ) % 80;
        int l = e / (IQ * 80);
        g_xpT[e] = xp_w[((size_t)l * IQ + k) * 80 + o];
    }
}

// ---------------- input MLP ----------------
__global__ void k_in_mlp(const float* __restrict__ x,
                         const float* __restrict__ iw1, const float* __restrict__ ib1,
                         const float* __restrict__ iw2, const float* __restrict__ ib2,
                         const float* __restrict__ iw3, const float* __restrict__ ib3) {
    int r = blockIdx.x, tid = threadIdx.x;
    __shared__ float xr[13];
    __shared__ float h1[256];
    __shared__ float h2[256];
    if (tid < 13) xr[tid] = x[r * 13 + tid];
    __syncthreads();
    float a = ib1[tid];
#pragma unroll
    for (int k = 0; k < 13; k++) a += xr[k] * iw1[k * 256 + tid];
    h1[tid] = fmaxf(a, 0.f);
    __syncthreads();
    a = ib2[tid];
    for (int k = 0; k < 256; k++) a += h1[k] * iw2[k * 256 + tid];
    h2[tid] = fmaxf(a, 0.f);
    __syncthreads();
#pragma unroll
    for (int ii = 0; ii < 3; ii++) {
        int c = tid + ii * 256;
        float v = ib3[c];
        for (int k = 0; k < 256; k++) v += h2[k] * iw3[k * 768 + c];
        g_h[r * 768 + c] = v;
    }
}

// ---------------- rmsnorm + tf32 hi/lo pre-split (block per row) ------------
__global__ void k_anorm(const float* __restrict__ norm_w, int l) {
    int r = blockIdx.x, tid = threadIdx.x;
    __shared__ float red[8];
    float v0 = g_h[r * 768 + tid];
    float v1 = g_h[r * 768 + 256 + tid];
    float v2 = g_h[r * 768 + 512 + tid];
    float ss = v0 * v0 + v1 * v1 + v2 * v2;
#pragma unroll
    for (int o = 16; o > 0; o >>= 1) ss += __shfl_xor_sync(0xffffffffu, ss, o);
    if ((tid & 31) == 0) red[tid >> 5] = ss;
    __syncthreads();
    float tot = red[0] + red[1] + red[2] + red[3] + red[4] + red[5] + red[6] + red[7];
    float rstd = rsqrtf(tot * (1.f / 768.f) + 1e-5f);
    const float* nw = norm_w + l * 768;
#pragma unroll
    for (int ii = 0; ii < 3; ii++) {
        int c = tid + ii * 256;
        float v = (ii == 0 ? v0 : (ii == 1 ? v1 : v2)) * rstd * nw[c];
        unsigned h = f2tf(v);
        g_anp[r * 768 + c] = make_uint2(h, f2tf(v - __uint_as_float(h)));
    }
}

// ---------------- in-proj GEMM (tf32 TC, pre-packed A, KTILE=32) ------------
// grid (24,15), 256 thr; block tile 16x128
__global__ void __launch_bounds__(256, 1) k_gemm_in(const float* __restrict__ in_w, int l) {
    __shared__ uint2 Apk[2][16][36];   //  9.2 KB
    __shared__ float Ws [2][32][132];  // 33.8 KB
    const float* W = in_w + (size_t)l * 768 * 3072;
    int tid = threadIdx.x;
    int col0 = blockIdx.x * 128, row0 = blockIdx.y * 16;
    unsigned aA = su32(Apk), aW = su32(Ws);
    int arr = tid >> 4, af2 = (tid & 15) * 2;
    const uint2* asrc = &g_anp[(size_t)(row0 + arr) * 768 + af2];

#define ISSUE_IN(s, k0) do { \
    CPA16(aA + (unsigned)((((s) * 16 + arr) * 36 + af2) * 8), asrc + (k0)); \
    _Pragma("unroll") \
    for (int p = 0; p < 4; p++) { int e = tid + p * 256; int kk = e >> 5, cc = (e & 31) * 4; \
        CPA16(aW + (unsigned)((((s) * 32 + kk) * 132 + cc) * 4), &W[(size_t)((k0) + kk) * 3072 + col0 + cc]); } \
    CPCOMMIT(); } while (0)

    ISSUE_IN(0, 0);
    int lane = tid & 31, wid = tid >> 5;
    int n0 = wid * 16;
    int g = lane >> 2, tg = lane & 3;
    float acc0[4] = {0, 0, 0, 0};
    float acc1[4] = {0, 0, 0, 0};
#pragma unroll 1
    for (int kt = 0; kt < 24; kt++) {
        __syncthreads();
        if (kt < 23) ISSUE_IN((kt + 1) & 1, (kt + 1) * 32); else CPCOMMIT();
        CPWAIT1();
        __syncthreads();
        int s = kt & 1;
#pragma unroll
        for (int ks = 0; ks < 4; ks++) {
            int kb = ks * 8;
            uint2 a0 = Apk[s][g][kb + tg];
            uint2 a1 = Apk[s][g + 8][kb + tg];
            uint2 a2 = Apk[s][g][kb + tg + 4];
            uint2 a3 = Apk[s][g + 8][kb + tg + 4];
            unsigned ah[4] = {a0.x, a1.x, a2.x, a3.x};
            unsigned al[4] = {a0.y, a1.y, a2.y, a3.y};
#pragma unroll
            for (int nf = 0; nf < 2; nf++) {
                int nc = n0 + nf * 8 + g;
                float bf0 = Ws[s][kb + tg][nc];
                float bf1 = Ws[s][kb + tg + 4][nc];
                unsigned bh0 = f2tf(bf0), bl0 = f2tf(bf0 - __uint_as_float(bh0));
                unsigned bh1 = f2tf(bf1), bl1 = f2tf(bf1 - __uint_as_float(bh1));
                float* acc = nf ? acc1 : acc0;
                MMA8(acc, ah, bh0, bh1);
                MMA8(acc, ah, bl0, bl1);
                MMA8(acc, al, bh0, bh1);
            }
        }
    }
#pragma unroll
    for (int nf = 0; nf < 2; nf++) {
        const float* acc = nf ? acc1 : acc0;
        int c = col0 + n0 + nf * 8 + tg * 2;
        size_t o0 = (size_t)(row0 + g) * 3072 + c;
        size_t o1 = (size_t)(row0 + g + 8) * 3072 + c;
        g_io[o0] = acc[0]; g_io[o0 + 1] = acc[1];
        g_io[o1] = acc[2]; g_io[o1 + 1] = acc[3];
    }
#undef ISSUE_IN
}

// ---------------- conv+silu+sp per row (coalesced transposed weights) -------
__global__ void __launch_bounds__(256) k_csp(const float* __restrict__ conv_w,
                                             const float* __restrict__ conv_b, int l) {
    __shared__ float hs2s[1536];
    int tid = threadIdx.x;
    int r = blockIdx.x, t = r % 60;
    int lane = tid & 31, w = tid >> 5;
    const float4* cw4 = (const float4*)(conv_w + (size_t)l * 1536 * 4);
    const float*  cb  = conv_b + l * 1536;
#pragma unroll
    for (int ii = 0; ii < 6; ii++) {
        int i = tid + ii * 256;
        float4 wv = cw4[i];
        const float* hsc = &g_io[(size_t)r * 3072 + i];
        float a = cb[i] + hsc[0] * wv.w;
        if (t >= 1) a += hsc[-3072] * wv.z;
        if (t >= 2) a += hsc[-6144] * wv.y;
        if (t >= 3) a += hsc[-9216] * wv.x;
        float v = a / (1.f + __expf(-a));
        hs2s[i] = v;
        g_hs2[(size_t)r * 1536 + i] = v;
    }
    __syncthreads();
    const float* WT = g_xpT + (size_t)l * 80 * 1536 + (size_t)w * 10 * 1536;
    float acc[10] = {0, 0, 0, 0, 0, 0, 0, 0, 0, 0};
#pragma unroll 2
    for (int k = lane; k < 1536; k += 32) {
        float h = hs2s[k];
#pragma unroll
        for (int j = 0; j < 10; j++) acc[j] = fmaf(h, WT[j * 1536 + k], acc[j]);
    }
#pragma unroll
    for (int j = 0; j < 10; j++) {
        float v = acc[j];
        v += __shfl_xor_sync(0xffffffffu, v, 16);
        v += __shfl_xor_sync(0xffffffffu, v, 8);
        v += __shfl_xor_sync(0xffffffffu, v, 4);
        v += __shfl_xor_sync(0xffffffffu, v, 2);
        v += __shfl_xor_sync(0xffffffffu, v, 1);
        if (lane == 0) g_sp[r * 80 + w * 10 + j] = v;
    }
}

// ---------------- scan: fused dt-proj + softplus + gate + tf32 pack ---------
// recurrence: 256 threads, thread = (channel, n-eighth), 2 states each
__global__ void __launch_bounds__(256) k_scan(const float* __restrict__ A_log,
                                              const float* __restrict__ Dp,
                                              const float* __restrict__ dt_w,
                                              const float* __restrict__ dt_b, int l) {
    __shared__ float ssp[60][80];
    __shared__ float shs[60][32];
    __shared__ float sdt[60][32];
    __shared__ float sWd[48][32];
    __shared__ float sdb[32];
    int tid = threadIdx.x;
    int b = blockIdx.x / 48, ic = blockIdx.x % 48, i0 = ic * 32;

    for (int e = tid; e < 1200; e += 256)
        ((float4*)ssp)[e] = ((const float4*)(g_sp + b * 60 * 80))[e];
    for (int e = tid; e < 1920; e += 256) {
        int t = e >> 5, j = e & 31;
        shs[t][j] = g_hs2[(size_t)(b * 60 + t) * 1536 + i0 + j];
    }
    const float* Wd = dt_w + (size_t)l * 48 * 1536;
    for (int e = tid; e < 1536; e += 256) {
        int k = e >> 5, j = e & 31;
        sWd[k][j] = Wd[(size_t)k * 1536 + i0 + j];
    }
    if (tid < 32) sdb[tid] = dt_b[l * 1536 + i0 + tid];
    __syncthreads();

    for (int e = tid; e < 1920; e += 256) {
        int t = e >> 5, j = e & 31;
        float d = sdb[j];
#pragma unroll
        for (int k = 0; k < 48; k++) d = fmaf(ssp[t][k], sWd[k][j], d);
        d = (d > 15.f) ? d : log1pf(__expf(d));
        sdt[t][j] = d;
    }
    __syncthreads();

    {
        int p = tid >> 3, nq = tid & 7;     // channel, n-eighth
        int i = i0 + p;
        float A[2], st[2] = {0, 0};
        const float* Ap = &A_log[((size_t)l * 1536 + i) * 16 + nq * 2];
        A[0] = -__expf(Ap[0]);
        A[1] = -__expf(Ap[1]);
        float Dv = Dp[l * 1536 + i];

        for (int t = 0; t < 60; t++) {
            float dtv = sdt[t][p], hsv = shs[t][p];
            float du = dtv * hsv;
            float ys = 0.f;
#pragma unroll
            for (int j = 0; j < 2; j++) {
                float dA = __expf(dtv * A[j]);
                st[j] = fmaf(dA, st[j], du * ssp[t][48 + nq * 2 + j]);
                ys = fmaf(st[j], ssp[t][64 + nq * 2 + j], ys);
            }
            // shfl_xor is a convergence point: the sdt[t][p] read above is
            // complete in all lanes before the nq==0 write below.
            ys += __shfl_xor_sync(0xffffffffu, ys, 1);
            ys += __shfl_xor_sync(0xffffffffu, ys, 2);
            ys += __shfl_xor_sync(0xffffffffu, ys, 4);
            if (nq == 0) sdt[t][p] = ys + hsv * Dv;
        }
    }
    __syncthreads();

    for (int e = tid; e < 1920; e += 256) {
        int t = e >> 5, j = e & 31;
        float g = g_io[(size_t)(b * 60 + t) * 3072 + 1536 + i0 + j];
        float sg = g / (1.f + __expf(-g));
        float v = sdt[t][j] * sg;
        unsigned h = f2tf(v);
        g_ycp[(size_t)(b * 60 + t) * 1536 + i0 + j] = make_uint2(h, f2tf(v - __uint_as_float(h)));
    }
}

// ---------------- out-proj GEMM (tf32 TC, pre-packed A, 16x64 tile) ---------
// grid (12,15), 256 thr; KTILE=32, 48 k-tiles
__global__ void __launch_bounds__(256) k_gemm_out(const float* __restrict__ out_w, int l) {
    __shared__ uint2 Apk[2][16][36];   //  9.2 KB
    __shared__ float Ws [2][32][68];   // 17.4 KB
    const float* W = out_w + (size_t)l * 1536 * 768;
    int tid = threadIdx.x;
    int col0 = blockIdx.x * 64, row0 = blockIdx.y * 16;
    unsigned aA = su32(Apk), aW = su32(Ws);
    int arr = tid >> 4, af2 = (tid & 15) * 2;
    const uint2* asrc = &g_ycp[(size_t)(row0 + arr) * 1536 + af2];

#define ISSUE_OUT(s, k0) do { \
    CPA16(aA + (unsigned)((((s) * 16 + arr) * 36 + af2) * 8), asrc + (k0)); \
    _Pragma("unroll") \
    for (int p = 0; p < 2; p++) { int e = tid + p * 256; int kk = e >> 4, cc = (e & 15) * 4; \
        CPA16(aW + (unsigned)((((s) * 32 + kk) * 68 + cc) * 4), &W[(size_t)((k0) + kk) * 768 + col0 + cc]); } \
    CPCOMMIT(); } while (0)

    ISSUE_OUT(0, 0);
    int lane = tid & 31, wid = tid >> 5;
    int n0 = wid * 8;
    int g = lane >> 2, tg = lane & 3;
    float acc[4] = {0, 0, 0, 0};
#pragma unroll 1
    for (int kt = 0; kt < 48; kt++) {
        __syncthreads();
        if (kt < 47) ISSUE_OUT((kt + 1) & 1, (kt + 1) * 32); else CPCOMMIT();
        CPWAIT1();
        __syncthreads();
        int s = kt & 1;
#pragma unroll
        for (int ks = 0; ks < 4; ks++) {
            int kb = ks * 8;
            uint2 a0 = Apk[s][g][kb + tg];
            uint2 a1 = Apk[s][g + 8][kb + tg];
            uint2 a2 = Apk[s][g][kb + tg + 4];
            uint2 a3 = Apk[s][g + 8][kb + tg + 4];
            unsigned ah[4] = {a0.x, a1.x, a2.x, a3.x};
            unsigned al[4] = {a0.y, a1.y, a2.y, a3.y};
            int nc = n0 + g;
            float bf0 = Ws[s][kb + tg][nc];
            float bf1 = Ws[s][kb + tg + 4][nc];
            unsigned bh0 = f2tf(bf0), bl0 = f2tf(bf0 - __uint_as_float(bh0));
            unsigned bh1 = f2tf(bf1), bl1 = f2tf(bf1 - __uint_as_float(bh1));
            MMA8(acc, ah, bh0, bh1);
            MMA8(acc, ah, bl0, bl1);
            MMA8(acc, al, bh0, bh1);
        }
    }
    {
        int c = col0 + n0 + tg * 2;
        size_t o0 = (size_t)(row0 + g) * 768 + c;
        size_t o1 = (size_t)(row0 + g + 8) * 768 + c;
        g_h[o0]     += acc[0];
        g_h[o0 + 1] += acc[1];
        g_h[o1]     += acc[2];
        g_h[o1 + 1] += acc[3];
    }
#undef ISSUE_OUT
}

// ---------------- final rmsnorm + attention logits --------------------------
__global__ void k_final(const float* __restrict__ fnorm_w,
                        const float* __restrict__ ws1, const float* __restrict__ ws2) {
    int r = blockIdx.x, tid = threadIdx.x;
    __shared__ float hf[768];
    __shared__ float al[128];
    __shared__ float red[256];
    float ss = 0.f;
    for (int k = tid; k < 768; k += 256) { float v = g_h[r * 768 + k]; ss += v * v; }
    red[tid] = ss;
    __syncthreads();
    for (int s = 128; s > 0; s >>= 1) { if (tid < s) red[tid] += red[tid + s]; __syncthreads(); }
    float rstd = rsqrtf(red[0] * (1.f / 768.f) + 1e-5f);
#pragma unroll
    for (int ii = 0; ii < 3; ii++) {
        int c = tid + ii * 256;
        float v = g_h[r * 768 + c] * rstd * fnorm_w[c];
        hf[c] = v;
        g_hf[r * 768 + c] = v;
    }
    __syncthreads();
    if (tid < 128) {
        float a = 0.f;
        for (int k = 0; k < 768; k++) a += hf[k] * ws1[k * 128 + tid];
        al[tid] = tanhf(a);
    }
    __syncthreads();
    if (tid < 4) {
        float s = 0.f;
        for (int d = 0; d < 128; d++) s += al[d] * ws2[d * 4 + tid];
        g_sc[r * 4 + tid] = s;
    }
}

// ---------------- softmax + pooling ----------------
__global__ void k_pool() {
    int b = blockIdx.x >> 2, rr = blockIdx.x & 3;
    int tid = threadIdx.x;
    __shared__ float att[60];
    __shared__ float mx_s, inv_s;
    if (tid < 60) att[tid] = g_sc[(b * 60 + tid) * 4 + rr];
    __syncthreads();
    if (tid == 0) {
        float m = -1e30f;
        for (int t = 0; t < 60; t++) m = fmaxf(m, att[t]);
        mx_s = m;
    }
    __syncthreads();
    if (tid < 60) att[tid] = __expf(att[tid] - mx_s);
    __syncthreads();
    if (tid == 0) {
        float s = 0.f;
        for (int t = 0; t < 60; t++) s += att[t];
        inv_s = 1.f / s;
    }
    __syncthreads();
    for (int c = tid; c < 768; c += 256) {
        float acc = 0.f;
        for (int t = 0; t < 60; t++) acc += att[t] * g_hf[(b * 60 + t) * 768 + c];
        g_m[b * 3072 + rr * 768 + c] = acc * inv_s;
    }
}

// ---------------- output MLP ----------------
__global__ void k_out_mlp(const float* __restrict__ ow1, const float* __restrict__ ob1,
                          const float* __restrict__ ow2, const float* __restrict__ ob2,
                          const float* __restrict__ ow3, const float* __restrict__ ob3,
                          float* __restrict__ out) {
    int b = blockIdx.x, tid = threadIdx.x;
    __shared__ float o1[256];
    __shared__ float o2[256];
    __shared__ float red[256];
    float a = ob1[tid];
    for (int k = 0; k < 3072; k++) a += g_m[b * 3072 + k] * ow1[k * 256 + tid];
    o1[tid] = fmaxf(a, 0.f);
    __syncthreads();
    a = ob2[tid];
    for (int k = 0; k < 256; k++) a += o1[k] * ow2[k * 256 + tid];
    o2[tid] = fmaxf(a, 0.f);
    __syncthreads();
    red[tid] = o2[tid] * ow3[tid];
    __syncthreads();
    for (int s = 128; s > 0; s >>= 1) { if (tid < s) red[tid] += red[tid + s]; __syncthreads(); }
    if (tid == 0) out[b] = red[0] + ob3[0];
}

// ---------------- launch ----------------
extern "C" void kernel_launch(void* const* d_in, const int* in_sizes, int n_in,
                              void* d_out, int out_size) {
    const float* x      = (const float*)d_in[0];
    const float* iw1    = (const float*)d_in[1];
    const float* ib1    = (const float*)d_in[2];
    const float* iw2    = (const float*)d_in[3];
    const float* ib2    = (const float*)d_in[4];
    const float* iw3    = (const float*)d_in[5];
    const float* ib3    = (const float*)d_in[6];
    const float* norm_w = (const float*)d_in[7];
    const float* in_w   = (const float*)d_in[8];
    const float* conv_w = (const float*)d_in[9];
    const float* conv_b = (const float*)d_in[10];
    const float* xp_w   = (const float*)d_in[11];
    const float* dt_w   = (const float*)d_in[12];
    const float* dt_b   = (const float*)d_in[13];
    const float* A_log  = (const float*)d_in[14];
    const float* Dp     = (const float*)d_in[15];
    const float* out_w  = (const float*)d_in[16];
    const float* fnorm_w= (const float*)d_in[17];
    const float* ws1    = (const float*)d_in[18];
    const float* ws2    = (const float*)d_in[19];
    const float* ow1    = (const float*)d_in[20];
    const float* ob1    = (const float*)d_in[21];
    const float* ow2    = (const float*)d_in[22];
    const float* ob2    = (const float*)d_in[23];
    const float* ow3    = (const float*)d_in[24];
    const float* ob3    = (const float*)d_in[25];

    k_in_mlp<<<BL, 256>>>(x, iw1, ib1, iw2, ib2, iw3, ib3);
    k_xt<<<(NLYR * 80 * IQ + 255) / 256, 256>>>(xp_w);

    for (int l = 0; l < NLYR; l++) {
        k_anorm<<<BL, 256>>>(norm_w, l);
        k_gemm_in<<<dim3(24, 15), 256>>>(in_w, l);
        k_csp<<<BL, 256>>>(conv_w, conv_b, l);
        k_scan<<<192, 256>>>(A_log, Dp, dt_w, dt_b, l);
        k_gemm_out<<<dim3(12, 15), 256>>>(out_w, l);
    }
    k_final<<<BL, 256>>>(fnorm_w, ws1, ws2);
    k_pool<<<16, 256>>>();
    k_out_mlp<<<4, 256>>>(ow1, ob1, ow2, ob2, ow3, ob3, (float*)d_out);
}